// round 15
// baseline (speedup 1.0000x reference)
#include <cuda_runtime.h>
#include <cuda_bf16.h>
#include <cstdint>

// Problem constants
#define BB   4
#define LL   2048
#define DM   1024
#define DI   2048
#define NM   (BB*LL)      // 8192 tokens
#define XZW  4096         // per-dir 2*DI
#define XZC  8192         // concat row width (both dirs)
#define PRW  96           // dt_rank + 2*d_state
#define DTR  64
#define DS   16

typedef __nv_bfloat16 bf16;
typedef __nv_bfloat162 bf162;

// ---------------- scratch (device globals; allocation-free rule) -------------
__device__ bf16  g_xn[(size_t)NM*DM];
__device__ bf16  g_xz[(size_t)NM*XZC];          // [token, fwd_x|fwd_z|bwd_x|bwd_z]
__device__ bf16  g_xc[2][(size_t)NM*DI];
__device__ float g_xpart[2][4][(size_t)NM*PRW];
__device__ bf16  g_projbf[2][(size_t)NM*PRW];
__device__ float g_delta[2][(size_t)NM*DI];
__device__ bf16  g_yg[2][(size_t)NM*DI];
__device__ bf16  g_ycat[(size_t)NM*DI];
__device__ bf16  g_wbf[15335424];               // all weights converted to bf16

__device__ __forceinline__ uint32_t pack_bf2(float x, float y){
    bf162 h = __float22bfloat162_rn(make_float2(x, y));
    return *(uint32_t*)&h;
}
__device__ __forceinline__ float2 unpack_bf2(uint32_t u){
    bf162 h = *(bf162*)&u;
    return __bfloat1622float2(h);
}

// ---------------- MUFU approx transcendentals --------------------------------
__device__ __forceinline__ float ex2a(float x){ float r; asm("ex2.approx.f32 %0, %1;" : "=f"(r) : "f"(x)); return r; }
__device__ __forceinline__ float lg2a(float x){ float r; asm("lg2.approx.f32 %0, %1;" : "=f"(r) : "f"(x)); return r; }
__device__ __forceinline__ float rcpa(float x){ float r; asm("rcp.approx.f32 %0, %1;" : "=f"(r) : "f"(x)); return r; }
#define L2E 1.4426950408889634f
#define LN2 0.6931471805599453f
__device__ __forceinline__ float sigm(float x){ return rcpa(1.f + ex2a(-L2E*x)); }

// ---------------- fused weight fp32 -> bf16 (all 9 weights, one launch) ------
__global__ __launch_bounds__(256) void cvt_all_kernel(
    const float* __restrict__ p0, const float* __restrict__ p1,
    const float* __restrict__ p2, const float* __restrict__ p3,
    const float* __restrict__ p4, const float* __restrict__ p5,
    const float* __restrict__ p6, const float* __restrict__ p7,
    const float* __restrict__ p8, bf16* __restrict__ out)
{
    size_t i = (size_t)blockIdx.x*256 + threadIdx.x;   // quad (float4) index
    if (i >= 3833856) return;
    const size_t cum[10] = {0,1048576,2097152,2146304,2195456,2228224,
                            2260992,2785280,3309568,3833856};
    const float* ps[9] = {p0,p1,p2,p3,p4,p5,p6,p7,p8};
    int seg = 0;
    #pragma unroll
    for (int s=0; s<9; s++) if (i >= cum[s+1]) seg = s+1;
    const float4* src = (const float4*)ps[seg];
    float4 v = src[i - cum[seg]];
    ((uint2*)out)[i] = make_uint2(pack_bf2(v.x, v.y), pack_bf2(v.z, v.w));
}

// ---------------- LayerNorm (fp32 in, bf16 out) ------------------------------
__global__ __launch_bounds__(256) void ln_kernel(
    const float* __restrict__ x, const float* __restrict__ gw,
    const float* __restrict__ bw, bf16* __restrict__ xn)
{
    __shared__ float red[16];
    int m = blockIdx.x, tid = threadIdx.x;
    const float4* xr = (const float4*)(x + (size_t)m*DM);
    float4 v = xr[tid];
    float s  = v.x+v.y+v.z+v.w;
    float ss = v.x*v.x+v.y*v.y+v.z*v.z+v.w*v.w;
    #pragma unroll
    for (int o=16;o;o>>=1){ s += __shfl_xor_sync(~0u,s,o); ss += __shfl_xor_sync(~0u,ss,o); }
    if ((tid&31)==0){ red[tid>>5]=s; red[8+(tid>>5)]=ss; }
    __syncthreads();
    if (tid<32){
        float a  = (tid<8)? red[tid]   : 0.f;
        float b2 = (tid<8)? red[8+tid] : 0.f;
        #pragma unroll
        for (int o=4;o;o>>=1){ a += __shfl_xor_sync(~0u,a,o); b2 += __shfl_xor_sync(~0u,b2,o); }
        if (tid==0){ red[0]=a; red[8]=b2; }
    }
    __syncthreads();
    float mu   = red[0]*(1.0f/DM);
    float var  = red[8]*(1.0f/DM) - mu*mu;
    float rstd = rsqrtf(var + 1e-5f);
    float4 g4 = ((const float4*)gw)[tid];
    float4 b4 = ((const float4*)bw)[tid];
    uint2 o = make_uint2(
        pack_bf2((v.x-mu)*rstd*g4.x + b4.x, (v.y-mu)*rstd*g4.y + b4.y),
        pack_bf2((v.z-mu)*rstd*g4.z + b4.z, (v.w-mu)*rstd*g4.w + b4.w));
    ((uint2*)(xn + (size_t)m*DM))[tid] = o;
}

// ---------------- BF16 tensor-core GEMM, NT ----------------------------------
// 128x128x64 tile, 8 warps, m16n8k16 bf16 mma, 3-stage cp.async pipeline.
// blockIdx.z batches via explicit strides: A += z*aBatch, B += z*bBatch, C += z*cBatch.
// EPI: 0 none, 1 softplus(acc+bias), 2 acc+bias+resid.
#define BKk 64
#define SROW 36          // row stride in u32: 32 (64 bf16) + 4 pad -> conflict-free
#define BUFU32 (128*SROW)
#define GSMEM (6*BUFU32*4)   // 3 stages x (A+B) x 18432B = 110592

__device__ __forceinline__ uint32_t smem_u32p(const void* p){
    return (uint32_t)__cvta_generic_to_shared(p);
}
__device__ __forceinline__ void ldsm4(uint32_t& r0, uint32_t& r1, uint32_t& r2, uint32_t& r3, uint32_t a){
    asm volatile("ldmatrix.sync.aligned.m8n8.x4.shared.b16 {%0,%1,%2,%3}, [%4];\n"
        : "=r"(r0), "=r"(r1), "=r"(r2), "=r"(r3) : "r"(a));
}
__device__ __forceinline__ void cp_async16(uint32_t dst, const void* src, int srcsize){
    asm volatile("cp.async.cg.shared.global [%0], [%1], 16, %2;\n"
        :: "r"(dst), "l"(src), "r"(srcsize));
}

template<int EPI, typename TOUT>
__global__ __launch_bounds__(256, 2) void gemm_bf16(
    const bf16* __restrict__ A, const bf16* __restrict__ B, TOUT* __restrict__ C,
    int M, int N, int K, int lda, int ldb, int ldc,
    size_t aBatch, size_t bBatch, size_t cBatch,
    const float* __restrict__ bias, const float* __restrict__ resid)
{
    extern __shared__ uint32_t sm[];
    uint32_t* As = sm;               // 3*BUFU32
    uint32_t* Bs = sm + 3*BUFU32;    // 3*BUFU32

    A += (size_t)blockIdx.z * aBatch;
    B += (size_t)blockIdx.z * bBatch;
    C += (size_t)blockIdx.z * cBatch;

    int tid  = threadIdx.x;
    int warp = tid >> 5, lane = tid & 31;
    int gid  = lane >> 2, tig = lane & 3;
    int wm   = (warp >> 1) * 32;
    int wn   = (warp & 1) * 64;
    int m0 = blockIdx.y * 128, n0 = blockIdx.x * 128;

    // staging: slot s (0..1023): row = s>>3, seg = s&7 (16B segment of 64-bf16 row)
    int srow[4], sseg[4];
    #pragma unroll
    for (int i=0;i<4;i++){ int s = tid + i*256; srow[i] = s>>3; sseg[i] = s&7; }

    auto issue = [&](int buf, int k0){
        uint32_t* Ab = As + buf*BUFU32;
        uint32_t* Bb = Bs + buf*BUFU32;
        #pragma unroll
        for (int i=0;i<4;i++){
            const bf16* sa = A + (size_t)(m0+srow[i])*lda + k0 + sseg[i]*8;
            cp_async16(smem_u32p(Ab + srow[i]*SROW + sseg[i]*4), sa, 16);
            int nrow = n0 + srow[i];
            const bf16* sb = B + (size_t)nrow*ldb + k0 + sseg[i]*8;
            cp_async16(smem_u32p(Bb + srow[i]*SROW + sseg[i]*4), sb, (nrow<N)?16:0);
        }
        asm volatile("cp.async.commit_group;\n" ::: "memory");
    };

    int g = lane >> 3, r = lane & 7;
    uint32_t aBase[2], bBase[4];
    #pragma unroll
    for (int mt=0;mt<2;mt++)
        aBase[mt] = smem_u32p(&As[(wm + mt*16 + (g&1)*8 + r)*SROW + (g>>1)*4]);
    #pragma unroll
    for (int p=0;p<4;p++)
        bBase[p] = smem_u32p(&Bs[(wn + p*16 + (g>>1)*8 + r)*SROW + (g&1)*4]);

    float acc[2][8][4];
    #pragma unroll
    for (int mt=0;mt<2;mt++)
        #pragma unroll
        for (int nt=0;nt<8;nt++)
            #pragma unroll
            for (int q=0;q<4;q++) acc[mt][nt][q]=0.f;

    int nchunk = K / BKk;
    issue(0, 0);
    if (nchunk > 1) issue(1, BKk);

    for (int ck=0; ck<nchunk; ck++){
        if (ck+1 < nchunk) asm volatile("cp.async.wait_group 1;\n" ::: "memory");
        else               asm volatile("cp.async.wait_group 0;\n" ::: "memory");
        __syncthreads();
        if (ck+2 < nchunk) issue((ck+2)%3, (ck+2)*BKk);

        uint32_t bufOff = (uint32_t)(ck%3) * (BUFU32*4);
        #pragma unroll
        for (int ks=0; ks<4; ks++){
            uint32_t kOff = bufOff + ks*32;   // 16 bf16 = 32 bytes
            uint32_t af[2][4];
            #pragma unroll
            for (int mt=0;mt<2;mt++)
                ldsm4(af[mt][0], af[mt][1], af[mt][2], af[mt][3], aBase[mt] + kOff);
            uint32_t bf[8][2];
            #pragma unroll
            for (int p=0;p<4;p++)
                ldsm4(bf[2*p][0], bf[2*p][1], bf[2*p+1][0], bf[2*p+1][1], bBase[p] + kOff);
            #pragma unroll
            for (int mt=0;mt<2;mt++)
                #pragma unroll
                for (int nt=0;nt<8;nt++){
                    asm volatile(
                        "mma.sync.aligned.m16n8k16.row.col.f32.bf16.bf16.f32 "
                        "{%0,%1,%2,%3}, {%4,%5,%6,%7}, {%8,%9}, {%0,%1,%2,%3};\n"
                        : "+f"(acc[mt][nt][0]), "+f"(acc[mt][nt][1]),
                          "+f"(acc[mt][nt][2]), "+f"(acc[mt][nt][3])
                        : "r"(af[mt][0]), "r"(af[mt][1]), "r"(af[mt][2]), "r"(af[mt][3]),
                          "r"(bf[nt][0]), "r"(bf[nt][1]));
                }
        }
    }

    // Epilogue: acc[mt][nt]: rows (gid, gid+8), cols (tig*2, tig*2+1)
    #pragma unroll
    for (int mt=0;mt<2;mt++){
        int r0 = m0 + wm + mt*16 + gid;
        #pragma unroll
        for (int nt=0;nt<8;nt++){
            int c = n0 + wn + nt*8 + tig*2;
            if (c >= N) continue;
            float v[4];
            #pragma unroll
            for (int q=0;q<4;q++) v[q] = acc[mt][nt][q];
            if (EPI==1){
                #pragma unroll
                for (int q=0;q<4;q++){
                    float t = v[q] + bias[c + (q&1)];
                    v[q] = (t > 20.f) ? t : LN2 * lg2a(1.f + ex2a(L2E*t));
                }
            }
            if (EPI==2){
                v[0] += bias[c]   + resid[(size_t)r0*ldc + c];
                v[1] += bias[c+1] + resid[(size_t)r0*ldc + c+1];
                v[2] += bias[c]   + resid[(size_t)(r0+8)*ldc + c];
                v[3] += bias[c+1] + resid[(size_t)(r0+8)*ldc + c+1];
            }
            if (sizeof(TOUT) == 4){
                *(float2*)((float*)C + (size_t)r0*ldc + c)     = make_float2(v[0], v[1]);
                *(float2*)((float*)C + (size_t)(r0+8)*ldc + c) = make_float2(v[2], v[3]);
            } else {
                *(uint32_t*)((bf16*)C + (size_t)r0*ldc + c)     = pack_bf2(v[0], v[1]);
                *(uint32_t*)((bf16*)C + (size_t)(r0+8)*ldc + c) = pack_bf2(v[2], v[3]);
            }
        }
    }
}

// ---------------- split-K reduce: 4 fp32 slabs -> bf16 -----------------------
__global__ __launch_bounds__(256) void reduce4_kernel(
    const float* __restrict__ part, bf16* __restrict__ out, int n)
{
    int i = blockIdx.x*256 + threadIdx.x;
    if (i < n){
        float s = part[i] + part[i+n] + part[i+2*n] + part[i+3*n];
        out[i] = __float2bfloat16(s);
    }
}

// ---------------- Depthwise conv + bias + SiLU, time-tiled, both dirs --------
__global__ __launch_bounds__(256) void conv2_kernel(
    const bf16* __restrict__ xz, const float* __restrict__ cw0,
    const float* __restrict__ cw1, const float* __restrict__ cb0,
    const float* __restrict__ cb1, bf16* __restrict__ xc_b)
{
    int dp = blockIdx.x*256 + threadIdx.x;   // 0..1023 channel pairs
    int d0 = dp*2;
    int t0 = blockIdx.y*8;
    int z = blockIdx.z;
    int dir = z >> 2, b = z & 3;
    bf16* xc = xc_b + (size_t)dir*NM*DI;
    const float* cw = dir ? cw1 : cw0;
    const float* cb = dir ? cb1 : cb0;
    float4 wa = *(const float4*)(cw + d0*4);
    float4 wb = *(const float4*)(cw + d0*4 + 4);
    float cba = cb[d0], cbb = cb[d0+1];
    size_t rowb = (size_t)b*LL;
    size_t coff = (size_t)dir*XZW + d0;

    float2 vals[11];
    #pragma unroll
    for (int j=0;j<11;j++){
        int t = dir ? (t0 + j) : (t0 - 3 + j);
        if (t >= 0 && t < LL){
            uint32_t u = *(const uint32_t*)(xz + (rowb + t)*XZC + coff);
            vals[j] = unpack_bf2(u);
        } else vals[j] = make_float2(0.f, 0.f);
    }
    #pragma unroll
    for (int i=0;i<8;i++){
        float ax, ay;
        if (!dir){
            ax = cba + wa.x*vals[i].x + wa.y*vals[i+1].x + wa.z*vals[i+2].x + wa.w*vals[i+3].x;
            ay = cbb + wb.x*vals[i].y + wb.y*vals[i+1].y + wb.z*vals[i+2].y + wb.w*vals[i+3].y;
        } else {
            ax = cba + wa.w*vals[i].x + wa.z*vals[i+1].x + wa.y*vals[i+2].x + wa.x*vals[i+3].x;
            ay = cbb + wb.w*vals[i].y + wb.z*vals[i+1].y + wb.y*vals[i+2].y + wb.x*vals[i+3].y;
        }
        float sx = ax * sigm(ax);
        float sy = ay * sigm(ay);
        *(uint32_t*)(xc + (rowb + t0 + i)*DI + d0) = pack_bf2(sx, sy);
    }
}

// ---------------- Selective scan: 8-deep register pipeline, MUFU ex2 ---------
// 4 thr/channel (4 states each), 8 channels/warp.
// B/C fetched by DIRECT 8B vector loads (each thread's 4 B's and 4 C's are
// contiguous bf16 in proj) -> no B/C shfls (were 8/step on the MIO pipe).
#define SU 8
__global__ __launch_bounds__(256) void scan2_kernel(
    const float* __restrict__ delta_b, const bf16* __restrict__ xc_b,
    const bf16* __restrict__ proj_b,  const bf16* __restrict__ xz,
    const float* __restrict__ A0, const float* __restrict__ A1,
    const float* __restrict__ D0, const float* __restrict__ D1,
    bf16* __restrict__ yg_b)
{
    int tid = threadIdx.x;
    int warp = tid >> 5, lane = tid & 31;
    int ch = lane >> 2, sg = lane & 3;
    int d = blockIdx.x*64 + warp*8 + ch;
    int b = blockIdx.y;
    int dir = blockIdx.z;
    const float* delta = delta_b + (size_t)dir*NM*DI;
    const bf16* xc    = xc_b    + (size_t)dir*NM*DI;
    const bf16* proj  = proj_b  + (size_t)dir*NM*PRW;
    const float* A_log = dir ? A1 : A0;
    float Dv = (dir ? D1 : D0)[d];
    bf16* yg = yg_b + (size_t)dir*NM*DI;
    float c[4], h[4];
    #pragma unroll
    for (int i=0;i<4;i++){
        c[i] = -expf(A_log[(size_t)d*DS + sg*4 + i]) * L2E;
        h[i] = 0.f;
    }
    size_t rowb = (size_t)b*LL;
    size_t zoff = (size_t)dir*XZW + DI + d;   // z-gate column in concat xz
    int boff = DTR + sg*4;                    // this thread's B quad in proj row
    int coff = DTR + DS + sg*4;               // this thread's C quad

    float Ad[SU], Ax[SU], Az[SU];
    uint2  ABq[SU], ACq[SU];
    float Bd[SU], Bx[SU], Bz[SU];
    uint2  BBq[SU], BCq[SU];

    auto loadblk = [&](int blk, float* pd, float* px, float* pz, uint2* pB, uint2* pC){
        #pragma unroll
        for (int j=0;j<SU;j++){
            int t = blk + j;
            size_t mm = rowb + (dir ? (LL-1-t) : t);
            pd[j] = delta[mm*DI + d];
            px[j] = __bfloat162float(xc[mm*DI + d]);
            pz[j] = __bfloat162float(xz[mm*XZC + zoff]);
            pB[j] = *(const uint2*)(proj + mm*PRW + boff);
            pC[j] = *(const uint2*)(proj + mm*PRW + coff);
        }
    };
    auto compute = [&](int blk, float* pd, float* px, float* pz, uint2* pB, uint2* pC){
        #pragma unroll
        for (int j=0;j<SU;j++){
            float dlt = pd[j], xv = px[j];
            float dx = dlt * xv;
            float2 b01 = unpack_bf2(pB[j].x);
            float2 b23 = unpack_bf2(pB[j].y);
            float2 c01 = unpack_bf2(pC[j].x);
            float2 c23 = unpack_bf2(pC[j].y);
            float Bv[4] = {b01.x, b01.y, b23.x, b23.y};
            float Cv[4] = {c01.x, c01.y, c23.x, c23.y};
            float y = 0.f;
            #pragma unroll
            for (int i=0;i<4;i++){
                float e = ex2a(dlt * c[i]);
                h[i] = fmaf(e, h[i], dx * Bv[i]);
                y = fmaf(h[i], Cv[i], y);
            }
            y += __shfl_xor_sync(~0u, y, 1);
            y += __shfl_xor_sync(~0u, y, 2);
            if (sg == 0){
                float zv = pz[j];
                float sz = zv * sigm(zv);
                int t = blk + j;
                size_t mm = rowb + (dir ? (LL-1-t) : t);
                yg[mm*DI + d] = __float2bfloat16((y + xv*Dv) * sz);
            }
        }
    };

    loadblk(0, Ad, Ax, Az, ABq, ACq);
    for (int blk = 0; blk < LL; blk += 2*SU){
        if (blk + SU < LL) loadblk(blk + SU, Bd, Bx, Bz, BBq, BCq);
        compute(blk, Ad, Ax, Az, ABq, ACq);
        if (blk + 2*SU < LL) loadblk(blk + 2*SU, Ad, Ax, Az, ABq, ACq);
        if (blk + SU < LL) compute(blk + SU, Bd, Bx, Bz, BBq, BCq);
    }
}

// ---------------- Host launcher ---------------------------------------------
extern "C" void kernel_launch(void* const* d_in, const int* in_sizes, int n_in,
                              void* d_out, int out_size)
{
    const float* X       = (const float*)d_in[0];
    const float* ln_g    = (const float*)d_in[1];
    const float* ln_b    = (const float*)d_in[2];
    const float* merge_w = (const float*)d_in[3];
    const float* merge_b = (const float*)d_in[4];

    bf16 *xn_p, *xz_p, *xc_p, *projbf_p, *yg_p, *ycat_p, *wbf_p;
    float *xpart_p, *delta_p;
    cudaGetSymbolAddress((void**)&xn_p,    g_xn);
    cudaGetSymbolAddress((void**)&xz_p,    g_xz);
    cudaGetSymbolAddress((void**)&xc_p,    g_xc);
    cudaGetSymbolAddress((void**)&xpart_p, g_xpart);
    cudaGetSymbolAddress((void**)&projbf_p,g_projbf);
    cudaGetSymbolAddress((void**)&delta_p, g_delta);
    cudaGetSymbolAddress((void**)&yg_p,    g_yg);
    cudaGetSymbolAddress((void**)&ycat_p,  g_ycat);
    cudaGetSymbolAddress((void**)&wbf_p,   g_wbf);

    cudaFuncSetAttribute(gemm_bf16<0,bf16>,  cudaFuncAttributeMaxDynamicSharedMemorySize, GSMEM);
    cudaFuncSetAttribute(gemm_bf16<0,float>, cudaFuncAttributeMaxDynamicSharedMemorySize, GSMEM);
    cudaFuncSetAttribute(gemm_bf16<1,float>, cudaFuncAttributeMaxDynamicSharedMemorySize, GSMEM);
    cudaFuncSetAttribute(gemm_bf16<2,float>, cudaFuncAttributeMaxDynamicSharedMemorySize, GSMEM);

    const float* W[2][9];
    for (int dir = 0; dir < 2; dir++)
        for (int i = 0; i < 9; i++)
            W[dir][i] = (const float*)d_in[5 + dir*9 + i];
    // 0 in_w, 1 conv_w, 2 conv_b, 3 xproj_w, 4 dt_w, 5 dt_b, 6 A_log, 7 D, 8 out_w

    // bf16 weight offsets (element units)
    const size_t o_in   = 0;                 // fwd in_w then bwd in_w (8192x1024)
    const size_t o_xp[2]  = {8388608, 8585216};
    const size_t o_dtw[2] = {8781824, 8912896};
    const size_t o_out[2] = {9043968, 11141120};
    const size_t o_mg     = 13238272;

    // 0. convert all weights to bf16 in one launch
    cvt_all_kernel<<<(3833856+255)/256, 256>>>(
        W[0][0], W[1][0], W[0][3], W[1][3], W[0][4], W[1][4],
        W[0][8], W[1][8], merge_w, wbf_p);

    // 1. LayerNorm -> bf16
    ln_kernel<<<NM, 256>>>(X, ln_g, ln_b, xn_p);

    // 2. in-proj BOTH dirs in one GEMM: [8192, 8192] K=1024 -> bf16 concat
    gemm_bf16<0,bf16><<<dim3(XZC/128, NM/128, 1), 256, GSMEM>>>(
        xn_p, wbf_p + o_in, xz_p,
        NM, XZC, DM, DM, DM, XZC, 0, 0, 0, nullptr, nullptr);

    // 3. depthwise conv + SiLU, both dirs, time-tiled
    conv2_kernel<<<dim3(4, LL/8, 2*BB), 256>>>(
        xz_p, W[0][1], W[1][1], W[0][2], W[1][2], xc_p);

    // 4. x-proj both dirs: [8192,96] K=2048, split-K=4 -> fp32 partials
    for (int dir = 0; dir < 2; dir++)
        gemm_bf16<0,float><<<dim3(1, NM/128, 4), 256, GSMEM>>>(
            xc_p + (size_t)dir*NM*DI, wbf_p + o_xp[dir],
            xpart_p + (size_t)dir*4*NM*PRW,
            NM, PRW, 512, DI, DI, PRW, 512, 512, (size_t)NM*PRW, nullptr, nullptr);

    // 4b. reduce partials -> bf16 proj
    for (int dir = 0; dir < 2; dir++)
        reduce4_kernel<<<(NM*PRW+255)/256, 256>>>(
            xpart_p + (size_t)dir*4*NM*PRW, projbf_p + (size_t)dir*NM*PRW, NM*PRW);

    // 5. delta both dirs: softplus(dt @ dt_w.T + dt_b)  [8192,2048] K=64
    for (int dir = 0; dir < 2; dir++)
        gemm_bf16<1,float><<<dim3(DI/128, NM/128, 1), 256, GSMEM>>>(
            projbf_p + (size_t)dir*NM*PRW, wbf_p + o_dtw[dir], delta_p + (size_t)dir*NM*DI,
            NM, DI, DTR, PRW, DTR, DI, 0, 0, 0, W[dir][5], nullptr);

    // 6. selective scan + gate, both dirs, deep-prefetch, shfl-free B/C
    scan2_kernel<<<dim3(DI/64, BB, 2), 256>>>(
        delta_p, xc_p, projbf_p, xz_p,
        W[0][6], W[1][6], W[0][7], W[1][7], yg_p);

    // 7. out-proj BOTH dirs batched via grid.z: [8192,1024] K=2048 -> bf16 concat
    gemm_bf16<0,bf16><<<dim3(DM/128, NM/128, 2), 256, GSMEM>>>(
        yg_p, wbf_p + o_out[0], ycat_p,
        NM, DM, DI, DI, DI, DI,
        (size_t)NM*DI, o_out[1]-o_out[0], (size_t)DM, nullptr, nullptr);

    // 8. merge + bias + residual -> fp32 out
    gemm_bf16<2,float><<<dim3(DM/128, NM/128, 1), 256, GSMEM>>>(
        ycat_p, wbf_p + o_mg, (float*)d_out, NM, DM, DI, DI, DI, DM, 0, 0, 0, merge_b, X);
}

// round 16
// speedup vs baseline: 1.1991x; 1.1991x over previous
#include <cuda_runtime.h>
#include <cuda_bf16.h>
#include <cstdint>

// Problem constants
#define BB   4
#define LL   2048
#define DM   1024
#define DI   2048
#define NM   (BB*LL)      // 8192 tokens
#define XZW  4096         // per-dir 2*DI
#define XZC  8192         // concat row width (both dirs)
#define PRW  96           // dt_rank + 2*d_state
#define DTR  64
#define DS   16

typedef __nv_bfloat16 bf16;
typedef __nv_bfloat162 bf162;

// ---------------- scratch (device globals; allocation-free rule) -------------
__device__ bf16  g_xn[(size_t)NM*DM];
__device__ bf16  g_xz[(size_t)NM*XZC];          // [token, fwd_x|fwd_z|bwd_x|bwd_z]
__device__ bf16  g_xc[2][(size_t)NM*DI];
__device__ float g_xpart[2][4][(size_t)NM*PRW];
__device__ bf16  g_projbf[2][(size_t)NM*PRW];
__device__ float g_delta[2][(size_t)NM*DI];
__device__ bf16  g_yg[2][(size_t)NM*DI];
__device__ bf16  g_ycat[(size_t)NM*DI];
__device__ bf16  g_wbf[15335424];               // all weights converted to bf16

__device__ __forceinline__ uint32_t pack_bf2(float x, float y){
    bf162 h = __float22bfloat162_rn(make_float2(x, y));
    return *(uint32_t*)&h;
}
__device__ __forceinline__ float2 unpack_bf2(uint32_t u){
    bf162 h = *(bf162*)&u;
    return __bfloat1622float2(h);
}

// ---------------- MUFU approx transcendentals --------------------------------
__device__ __forceinline__ float ex2a(float x){ float r; asm("ex2.approx.f32 %0, %1;" : "=f"(r) : "f"(x)); return r; }
__device__ __forceinline__ float lg2a(float x){ float r; asm("lg2.approx.f32 %0, %1;" : "=f"(r) : "f"(x)); return r; }
__device__ __forceinline__ float rcpa(float x){ float r; asm("rcp.approx.f32 %0, %1;" : "=f"(r) : "f"(x)); return r; }
#define L2E 1.4426950408889634f
#define LN2 0.6931471805599453f
__device__ __forceinline__ float sigm(float x){ return rcpa(1.f + ex2a(-L2E*x)); }

// ---------------- fused weight fp32 -> bf16 (all 9 weights, one launch) ------
__global__ __launch_bounds__(256) void cvt_all_kernel(
    const float* __restrict__ p0, const float* __restrict__ p1,
    const float* __restrict__ p2, const float* __restrict__ p3,
    const float* __restrict__ p4, const float* __restrict__ p5,
    const float* __restrict__ p6, const float* __restrict__ p7,
    const float* __restrict__ p8, bf16* __restrict__ out)
{
    size_t i = (size_t)blockIdx.x*256 + threadIdx.x;   // quad (float4) index
    if (i >= 3833856) return;
    const size_t cum[10] = {0,1048576,2097152,2146304,2195456,2228224,
                            2260992,2785280,3309568,3833856};
    const float* ps[9] = {p0,p1,p2,p3,p4,p5,p6,p7,p8};
    int seg = 0;
    #pragma unroll
    for (int s=0; s<9; s++) if (i >= cum[s+1]) seg = s+1;
    const float4* src = (const float4*)ps[seg];
    float4 v = src[i - cum[seg]];
    ((uint2*)out)[i] = make_uint2(pack_bf2(v.x, v.y), pack_bf2(v.z, v.w));
}

// ---------------- LayerNorm (fp32 in, bf16 out) ------------------------------
__global__ __launch_bounds__(256) void ln_kernel(
    const float* __restrict__ x, const float* __restrict__ gw,
    const float* __restrict__ bw, bf16* __restrict__ xn)
{
    __shared__ float red[16];
    int m = blockIdx.x, tid = threadIdx.x;
    const float4* xr = (const float4*)(x + (size_t)m*DM);
    float4 v = xr[tid];
    float s  = v.x+v.y+v.z+v.w;
    float ss = v.x*v.x+v.y*v.y+v.z*v.z+v.w*v.w;
    #pragma unroll
    for (int o=16;o;o>>=1){ s += __shfl_xor_sync(~0u,s,o); ss += __shfl_xor_sync(~0u,ss,o); }
    if ((tid&31)==0){ red[tid>>5]=s; red[8+(tid>>5)]=ss; }
    __syncthreads();
    if (tid<32){
        float a  = (tid<8)? red[tid]   : 0.f;
        float b2 = (tid<8)? red[8+tid] : 0.f;
        #pragma unroll
        for (int o=4;o;o>>=1){ a += __shfl_xor_sync(~0u,a,o); b2 += __shfl_xor_sync(~0u,b2,o); }
        if (tid==0){ red[0]=a; red[8]=b2; }
    }
    __syncthreads();
    float mu   = red[0]*(1.0f/DM);
    float var  = red[8]*(1.0f/DM) - mu*mu;
    float rstd = rsqrtf(var + 1e-5f);
    float4 g4 = ((const float4*)gw)[tid];
    float4 b4 = ((const float4*)bw)[tid];
    uint2 o = make_uint2(
        pack_bf2((v.x-mu)*rstd*g4.x + b4.x, (v.y-mu)*rstd*g4.y + b4.y),
        pack_bf2((v.z-mu)*rstd*g4.z + b4.z, (v.w-mu)*rstd*g4.w + b4.w));
    ((uint2*)(xn + (size_t)m*DM))[tid] = o;
}

// ---------------- BF16 tensor-core GEMM, NT ----------------------------------
// 128x128x64 tile, 8 warps, m16n8k16 bf16 mma, 3-stage cp.async pipeline.
// blockIdx.z batches via explicit strides. For EPI==1, blockIdx.z!=0 uses
// `resid` as the bias pointer (second direction's dt bias).
// EPI: 0 none, 1 softplus(acc+bias), 2 acc+bias+resid.
#define BKk 64
#define SROW 36          // row stride in u32: 32 (64 bf16) + 4 pad -> conflict-free
#define BUFU32 (128*SROW)
#define GSMEM (6*BUFU32*4)   // 3 stages x (A+B) x 18432B = 110592

__device__ __forceinline__ uint32_t smem_u32p(const void* p){
    return (uint32_t)__cvta_generic_to_shared(p);
}
__device__ __forceinline__ void ldsm4(uint32_t& r0, uint32_t& r1, uint32_t& r2, uint32_t& r3, uint32_t a){
    asm volatile("ldmatrix.sync.aligned.m8n8.x4.shared.b16 {%0,%1,%2,%3}, [%4];\n"
        : "=r"(r0), "=r"(r1), "=r"(r2), "=r"(r3) : "r"(a));
}
__device__ __forceinline__ void cp_async16(uint32_t dst, const void* src, int srcsize){
    asm volatile("cp.async.cg.shared.global [%0], [%1], 16, %2;\n"
        :: "r"(dst), "l"(src), "r"(srcsize));
}

template<int EPI, typename TOUT>
__global__ __launch_bounds__(256, 2) void gemm_bf16(
    const bf16* __restrict__ A, const bf16* __restrict__ B, TOUT* __restrict__ C,
    int M, int N, int K, int lda, int ldb, int ldc,
    size_t aBatch, size_t bBatch, size_t cBatch,
    const float* __restrict__ bias, const float* __restrict__ resid)
{
    extern __shared__ uint32_t sm[];
    uint32_t* As = sm;               // 3*BUFU32
    uint32_t* Bs = sm + 3*BUFU32;    // 3*BUFU32

    A += (size_t)blockIdx.z * aBatch;
    B += (size_t)blockIdx.z * bBatch;
    C += (size_t)blockIdx.z * cBatch;
    const float* bb = (EPI==1 && blockIdx.z) ? resid : bias;

    int tid  = threadIdx.x;
    int warp = tid >> 5, lane = tid & 31;
    int gid  = lane >> 2, tig = lane & 3;
    int wm   = (warp >> 1) * 32;
    int wn   = (warp & 1) * 64;
    int m0 = blockIdx.y * 128, n0 = blockIdx.x * 128;

    // staging: slot s (0..1023): row = s>>3, seg = s&7 (16B segment of 64-bf16 row)
    int srow[4], sseg[4];
    #pragma unroll
    for (int i=0;i<4;i++){ int s = tid + i*256; srow[i] = s>>3; sseg[i] = s&7; }

    auto issue = [&](int buf, int k0){
        uint32_t* Ab = As + buf*BUFU32;
        uint32_t* Bb = Bs + buf*BUFU32;
        #pragma unroll
        for (int i=0;i<4;i++){
            const bf16* sa = A + (size_t)(m0+srow[i])*lda + k0 + sseg[i]*8;
            cp_async16(smem_u32p(Ab + srow[i]*SROW + sseg[i]*4), sa, 16);
            int nrow = n0 + srow[i];
            const bf16* sb = B + (size_t)nrow*ldb + k0 + sseg[i]*8;
            cp_async16(smem_u32p(Bb + srow[i]*SROW + sseg[i]*4), sb, (nrow<N)?16:0);
        }
        asm volatile("cp.async.commit_group;\n" ::: "memory");
    };

    int g = lane >> 3, r = lane & 7;
    uint32_t aBase[2], bBase[4];
    #pragma unroll
    for (int mt=0;mt<2;mt++)
        aBase[mt] = smem_u32p(&As[(wm + mt*16 + (g&1)*8 + r)*SROW + (g>>1)*4]);
    #pragma unroll
    for (int p=0;p<4;p++)
        bBase[p] = smem_u32p(&Bs[(wn + p*16 + (g>>1)*8 + r)*SROW + (g&1)*4]);

    float acc[2][8][4];
    #pragma unroll
    for (int mt=0;mt<2;mt++)
        #pragma unroll
        for (int nt=0;nt<8;nt++)
            #pragma unroll
            for (int q=0;q<4;q++) acc[mt][nt][q]=0.f;

    int nchunk = K / BKk;
    issue(0, 0);
    if (nchunk > 1) issue(1, BKk);

    for (int ck=0; ck<nchunk; ck++){
        if (ck+1 < nchunk) asm volatile("cp.async.wait_group 1;\n" ::: "memory");
        else               asm volatile("cp.async.wait_group 0;\n" ::: "memory");
        __syncthreads();
        if (ck+2 < nchunk) issue((ck+2)%3, (ck+2)*BKk);

        uint32_t bufOff = (uint32_t)(ck%3) * (BUFU32*4);
        #pragma unroll
        for (int ks=0; ks<4; ks++){
            uint32_t kOff = bufOff + ks*32;   // 16 bf16 = 32 bytes
            uint32_t af[2][4];
            #pragma unroll
            for (int mt=0;mt<2;mt++)
                ldsm4(af[mt][0], af[mt][1], af[mt][2], af[mt][3], aBase[mt] + kOff);
            uint32_t bf[8][2];
            #pragma unroll
            for (int p=0;p<4;p++)
                ldsm4(bf[2*p][0], bf[2*p][1], bf[2*p+1][0], bf[2*p+1][1], bBase[p] + kOff);
            #pragma unroll
            for (int mt=0;mt<2;mt++)
                #pragma unroll
                for (int nt=0;nt<8;nt++){
                    asm volatile(
                        "mma.sync.aligned.m16n8k16.row.col.f32.bf16.bf16.f32 "
                        "{%0,%1,%2,%3}, {%4,%5,%6,%7}, {%8,%9}, {%0,%1,%2,%3};\n"
                        : "+f"(acc[mt][nt][0]), "+f"(acc[mt][nt][1]),
                          "+f"(acc[mt][nt][2]), "+f"(acc[mt][nt][3])
                        : "r"(af[mt][0]), "r"(af[mt][1]), "r"(af[mt][2]), "r"(af[mt][3]),
                          "r"(bf[nt][0]), "r"(bf[nt][1]));
                }
        }
    }

    // Epilogue: acc[mt][nt]: rows (gid, gid+8), cols (tig*2, tig*2+1)
    #pragma unroll
    for (int mt=0;mt<2;mt++){
        int r0 = m0 + wm + mt*16 + gid;
        #pragma unroll
        for (int nt=0;nt<8;nt++){
            int c = n0 + wn + nt*8 + tig*2;
            if (c >= N) continue;
            float v[4];
            #pragma unroll
            for (int q=0;q<4;q++) v[q] = acc[mt][nt][q];
            if (EPI==1){
                #pragma unroll
                for (int q=0;q<4;q++){
                    float t = v[q] + bb[c + (q&1)];
                    v[q] = (t > 20.f) ? t : LN2 * lg2a(1.f + ex2a(L2E*t));
                }
            }
            if (EPI==2){
                v[0] += bias[c]   + resid[(size_t)r0*ldc + c];
                v[1] += bias[c+1] + resid[(size_t)r0*ldc + c+1];
                v[2] += bias[c]   + resid[(size_t)(r0+8)*ldc + c];
                v[3] += bias[c+1] + resid[(size_t)(r0+8)*ldc + c+1];
            }
            if (sizeof(TOUT) == 4){
                *(float2*)((float*)C + (size_t)r0*ldc + c)     = make_float2(v[0], v[1]);
                *(float2*)((float*)C + (size_t)(r0+8)*ldc + c) = make_float2(v[2], v[3]);
            } else {
                *(uint32_t*)((bf16*)C + (size_t)r0*ldc + c)     = pack_bf2(v[0], v[1]);
                *(uint32_t*)((bf16*)C + (size_t)(r0+8)*ldc + c) = pack_bf2(v[2], v[3]);
            }
        }
    }
}

// ---------------- split-K reduce: 4 fp32 slabs -> bf16 -----------------------
__global__ __launch_bounds__(256) void reduce4_kernel(
    const float* __restrict__ part, bf16* __restrict__ out, int n)
{
    int i = blockIdx.x*256 + threadIdx.x;
    if (i < n){
        float s = part[i] + part[i+n] + part[i+2*n] + part[i+3*n];
        out[i] = __float2bfloat16(s);
    }
}

// ---------------- Depthwise conv + bias + SiLU, time-tiled, both dirs --------
__global__ __launch_bounds__(256) void conv2_kernel(
    const bf16* __restrict__ xz, const float* __restrict__ cw0,
    const float* __restrict__ cw1, const float* __restrict__ cb0,
    const float* __restrict__ cb1, bf16* __restrict__ xc_b)
{
    int dp = blockIdx.x*256 + threadIdx.x;   // 0..1023 channel pairs
    int d0 = dp*2;
    int t0 = blockIdx.y*8;
    int z = blockIdx.z;
    int dir = z >> 2, b = z & 3;
    bf16* xc = xc_b + (size_t)dir*NM*DI;
    const float* cw = dir ? cw1 : cw0;
    const float* cb = dir ? cb1 : cb0;
    float4 wa = *(const float4*)(cw + d0*4);
    float4 wb = *(const float4*)(cw + d0*4 + 4);
    float cba = cb[d0], cbb = cb[d0+1];
    size_t rowb = (size_t)b*LL;
    size_t coff = (size_t)dir*XZW + d0;

    float2 vals[11];
    #pragma unroll
    for (int j=0;j<11;j++){
        int t = dir ? (t0 + j) : (t0 - 3 + j);
        if (t >= 0 && t < LL){
            uint32_t u = *(const uint32_t*)(xz + (rowb + t)*XZC + coff);
            vals[j] = unpack_bf2(u);
        } else vals[j] = make_float2(0.f, 0.f);
    }
    #pragma unroll
    for (int i=0;i<8;i++){
        float ax, ay;
        if (!dir){
            ax = cba + wa.x*vals[i].x + wa.y*vals[i+1].x + wa.z*vals[i+2].x + wa.w*vals[i+3].x;
            ay = cbb + wb.x*vals[i].y + wb.y*vals[i+1].y + wb.z*vals[i+2].y + wb.w*vals[i+3].y;
        } else {
            ax = cba + wa.w*vals[i].x + wa.z*vals[i+1].x + wa.y*vals[i+2].x + wa.x*vals[i+3].x;
            ay = cbb + wb.w*vals[i].y + wb.z*vals[i+1].y + wb.y*vals[i+2].y + wb.x*vals[i+3].y;
        }
        float sx = ax * sigm(ax);
        float sy = ay * sigm(ay);
        *(uint32_t*)(xc + (rowb + t0 + i)*DI + d0) = pack_bf2(sx, sy);
    }
}

// ---------------- Selective scan: 8-deep register pipeline, MUFU ex2 ---------
// 4 thr/channel (4 states each), 8 channels/warp, BC via shfl (round-12 form).
#define SU 8
__global__ __launch_bounds__(256) void scan2_kernel(
    const float* __restrict__ delta_b, const bf16* __restrict__ xc_b,
    const bf16* __restrict__ proj_b,  const bf16* __restrict__ xz,
    const float* __restrict__ A0, const float* __restrict__ A1,
    const float* __restrict__ D0, const float* __restrict__ D1,
    bf16* __restrict__ yg_b)
{
    int tid = threadIdx.x;
    int warp = tid >> 5, lane = tid & 31;
    int ch = lane >> 2, sg = lane & 3;
    int d = blockIdx.x*64 + warp*8 + ch;
    int b = blockIdx.y;
    int dir = blockIdx.z;
    const float* delta = delta_b + (size_t)dir*NM*DI;
    const bf16* xc    = xc_b    + (size_t)dir*NM*DI;
    const bf16* proj  = proj_b  + (size_t)dir*NM*PRW;
    const float* A_log = dir ? A1 : A0;
    float Dv = (dir ? D1 : D0)[d];
    bf16* yg = yg_b + (size_t)dir*NM*DI;
    float c[4], h[4];
    #pragma unroll
    for (int i=0;i<4;i++){
        c[i] = -expf(A_log[(size_t)d*DS + sg*4 + i]) * L2E;
        h[i] = 0.f;
    }
    size_t rowb = (size_t)b*LL;
    size_t zoff = (size_t)dir*XZW + DI + d;   // z-gate column in concat xz

    float Ad[SU], Ax[SU], Az[SU], Ab[SU];
    float Bd[SU], Bx[SU], Bz[SU], Bb[SU];

    auto loadblk = [&](int blk, float* pd, float* px, float* pz, float* pb){
        #pragma unroll
        for (int j=0;j<SU;j++){
            int t = blk + j;
            size_t mm = rowb + (dir ? (LL-1-t) : t);
            pd[j] = delta[mm*DI + d];
            px[j] = __bfloat162float(xc[mm*DI + d]);
            pz[j] = __bfloat162float(xz[mm*XZC + zoff]);
            pb[j] = __bfloat162float(proj[mm*PRW + DTR + lane]);
        }
    };
    auto compute = [&](int blk, float* pd, float* px, float* pz, float* pb){
        #pragma unroll
        for (int j=0;j<SU;j++){
            float dlt = pd[j], xv = px[j];
            float dx = dlt * xv;
            float y = 0.f;
            #pragma unroll
            for (int i=0;i<4;i++){
                float Bv = __shfl_sync(~0u, pb[j], sg*4 + i);
                float Cv = __shfl_sync(~0u, pb[j], 16 + sg*4 + i);
                float e = ex2a(dlt * c[i]);
                h[i] = fmaf(e, h[i], dx * Bv);
                y = fmaf(h[i], Cv, y);
            }
            y += __shfl_xor_sync(~0u, y, 1);
            y += __shfl_xor_sync(~0u, y, 2);
            if (sg == 0){
                float zv = pz[j];
                float sz = zv * sigm(zv);
                int t = blk + j;
                size_t mm = rowb + (dir ? (LL-1-t) : t);
                yg[mm*DI + d] = __float2bfloat16((y + xv*Dv) * sz);
            }
        }
    };

    loadblk(0, Ad, Ax, Az, Ab);
    for (int blk = 0; blk < LL; blk += 2*SU){
        if (blk + SU < LL) loadblk(blk + SU, Bd, Bx, Bz, Bb);
        compute(blk, Ad, Ax, Az, Ab);
        if (blk + 2*SU < LL) loadblk(blk + 2*SU, Ad, Ax, Az, Ab);
        if (blk + SU < LL) compute(blk + SU, Bd, Bx, Bz, Bb);
    }
}

// ---------------- Host launcher ---------------------------------------------
extern "C" void kernel_launch(void* const* d_in, const int* in_sizes, int n_in,
                              void* d_out, int out_size)
{
    const float* X       = (const float*)d_in[0];
    const float* ln_g    = (const float*)d_in[1];
    const float* ln_b    = (const float*)d_in[2];
    const float* merge_w = (const float*)d_in[3];
    const float* merge_b = (const float*)d_in[4];

    bf16 *xn_p, *xz_p, *xc_p, *projbf_p, *yg_p, *ycat_p, *wbf_p;
    float *xpart_p, *delta_p;
    cudaGetSymbolAddress((void**)&xn_p,    g_xn);
    cudaGetSymbolAddress((void**)&xz_p,    g_xz);
    cudaGetSymbolAddress((void**)&xc_p,    g_xc);
    cudaGetSymbolAddress((void**)&xpart_p, g_xpart);
    cudaGetSymbolAddress((void**)&projbf_p,g_projbf);
    cudaGetSymbolAddress((void**)&delta_p, g_delta);
    cudaGetSymbolAddress((void**)&yg_p,    g_yg);
    cudaGetSymbolAddress((void**)&ycat_p,  g_ycat);
    cudaGetSymbolAddress((void**)&wbf_p,   g_wbf);

    cudaFuncSetAttribute(gemm_bf16<0,bf16>,  cudaFuncAttributeMaxDynamicSharedMemorySize, GSMEM);
    cudaFuncSetAttribute(gemm_bf16<0,float>, cudaFuncAttributeMaxDynamicSharedMemorySize, GSMEM);
    cudaFuncSetAttribute(gemm_bf16<1,float>, cudaFuncAttributeMaxDynamicSharedMemorySize, GSMEM);
    cudaFuncSetAttribute(gemm_bf16<2,float>, cudaFuncAttributeMaxDynamicSharedMemorySize, GSMEM);

    const float* W[2][9];
    for (int dir = 0; dir < 2; dir++)
        for (int i = 0; i < 9; i++)
            W[dir][i] = (const float*)d_in[5 + dir*9 + i];
    // 0 in_w, 1 conv_w, 2 conv_b, 3 xproj_w, 4 dt_w, 5 dt_b, 6 A_log, 7 D, 8 out_w

    // bf16 weight offsets (element units)
    const size_t o_in   = 0;                 // fwd in_w then bwd in_w (8192x1024)
    const size_t o_xp[2]  = {8388608, 8585216};
    const size_t o_dtw[2] = {8781824, 8912896};
    const size_t o_out[2] = {9043968, 11141120};
    const size_t o_mg     = 13238272;

    // 0. convert all weights to bf16 in one launch
    cvt_all_kernel<<<(3833856+255)/256, 256>>>(
        W[0][0], W[1][0], W[0][3], W[1][3], W[0][4], W[1][4],
        W[0][8], W[1][8], merge_w, wbf_p);

    // 1. LayerNorm -> bf16
    ln_kernel<<<NM, 256>>>(X, ln_g, ln_b, xn_p);

    // 2. in-proj BOTH dirs in one GEMM: [8192, 8192] K=1024 -> bf16 concat
    gemm_bf16<0,bf16><<<dim3(XZC/128, NM/128, 1), 256, GSMEM>>>(
        xn_p, wbf_p + o_in, xz_p,
        NM, XZC, DM, DM, DM, XZC, 0, 0, 0, nullptr, nullptr);

    // 3. depthwise conv + SiLU, both dirs, time-tiled
    conv2_kernel<<<dim3(4, LL/8, 2*BB), 256>>>(
        xz_p, W[0][1], W[1][1], W[0][2], W[1][2], xc_p);

    // 4. x-proj both dirs: [8192,96] K=2048, split-K=4 -> fp32 partials
    for (int dir = 0; dir < 2; dir++)
        gemm_bf16<0,float><<<dim3(1, NM/128, 4), 256, GSMEM>>>(
            xc_p + (size_t)dir*NM*DI, wbf_p + o_xp[dir],
            xpart_p + (size_t)dir*4*NM*PRW,
            NM, PRW, 512, DI, DI, PRW, 512, 512, (size_t)NM*PRW, nullptr, nullptr);

    // 4b. reduce partials -> bf16 proj
    for (int dir = 0; dir < 2; dir++)
        reduce4_kernel<<<(NM*PRW+255)/256, 256>>>(
            xpart_p + (size_t)dir*4*NM*PRW, projbf_p + (size_t)dir*NM*PRW, NM*PRW);

    // 5. delta BOTH dirs in one launch: softplus(dt @ dt_w.T + dt_b)
    //    grid.z selects dir; second dir's bias passed via `resid` slot.
    gemm_bf16<1,float><<<dim3(DI/128, NM/128, 2), 256, GSMEM>>>(
        projbf_p, wbf_p + o_dtw[0], delta_p,
        NM, DI, DTR, PRW, DTR, DI,
        (size_t)NM*PRW, o_dtw[1]-o_dtw[0], (size_t)NM*DI,
        W[0][5], W[1][5]);

    // 6. selective scan + gate, both dirs, deep-prefetch (round-12 form)
    scan2_kernel<<<dim3(DI/64, BB, 2), 256>>>(
        delta_p, xc_p, projbf_p, xz_p,
        W[0][6], W[1][6], W[0][7], W[1][7], yg_p);

    // 7. out-proj BOTH dirs batched via grid.z: [8192,1024] K=2048 -> bf16 concat
    gemm_bf16<0,bf16><<<dim3(DM/128, NM/128, 2), 256, GSMEM>>>(
        yg_p, wbf_p + o_out[0], ycat_p,
        NM, DM, DI, DI, DI, DI,
        (size_t)NM*DI, o_out[1]-o_out[0], (size_t)DM, nullptr, nullptr);

    // 8. merge + bias + residual -> fp32 out
    gemm_bf16<2,float><<<dim3(DM/128, NM/128, 1), 256, GSMEM>>>(
        ycat_p, wbf_p + o_mg, (float*)d_out, NM, DM, DI, DI, DI, DM, 0, 0, 0, merge_b, X);
}